// round 1
// baseline (speedup 1.0000x reference)
#include <cuda_runtime.h>

// Problem constants
#define C2    2048   // per-input channels (output rows of Q/K/V2)
#define NPIX  4096   // H*W
#define BATCH 2

// ---------------------------------------------------------------------------
// Scratch (static __device__ arrays -- no allocation anywhere)
// ---------------------------------------------------------------------------
__device__ float g_X  [(size_t)BATCH * 2 * C2 * NPIX];  // packed concat [b][4096][4096]
__device__ float g_Q  [(size_t)BATCH * C2 * NPIX];      // [b][2048][4096]
__device__ float g_K  [(size_t)BATCH * C2 * NPIX];
__device__ float g_V2 [(size_t)BATCH * C2 * NPIX];      // folded V (top+bottom halves)
__device__ float g_wv2[(size_t)C2 * 2 * C2];            // wv[:2048] + wv[2048:]
__device__ float g_bv2[C2];

// ---------------------------------------------------------------------------
// pack_copy: writes f_rgb/f_i copies into d_out AND packs concat X scratch
// ---------------------------------------------------------------------------
__global__ void pack_copy_kernel(const float4* __restrict__ frgb,
                                 const float4* __restrict__ fi,
                                 float4* __restrict__ out)
{
    const size_t PER = (size_t)BATCH * C2 * NPIX / 4;   // 4,194,304 float4 per tensor
    const size_t PB  = (size_t)C2 * NPIX / 4;           // per-batch float4
    size_t i = (size_t)blockIdx.x * blockDim.x + threadIdx.x;
    if (i >= PER) return;
    float4 r = frgb[i];
    float4 w = fi[i];
    out[PER + i]     = r;   // f_rgb copy  (after f_final region)
    out[2 * PER + i] = w;   // f_i copy
    size_t b = i / PB, rpos = i - b * PB;
    float4* X4 = reinterpret_cast<float4*>(g_X);
    X4[b * 2 * PB + rpos]      = r;
    X4[b * 2 * PB + PB + rpos] = w;
}

// ---------------------------------------------------------------------------
// wsum: fold wv/bv top+bottom halves (f_final = (V_top + V_bot) @ attn^T)
// ---------------------------------------------------------------------------
__global__ void wsum_kernel(const float4* __restrict__ wv,
                            const float4* __restrict__ bv)
{
    const size_t HALF = (size_t)C2 * 2 * C2 / 4;   // 2,097,152 float4
    size_t i = (size_t)blockIdx.x * blockDim.x + threadIdx.x;
    if (i < HALF) {
        float4 a = wv[i], b = wv[i + HALF], o;
        o.x = a.x + b.x; o.y = a.y + b.y; o.z = a.z + b.z; o.w = a.w + b.w;
        reinterpret_cast<float4*>(g_wv2)[i] = o;
    }
    if (i < C2 / 4) {
        float4 a = bv[i], b = bv[i + C2 / 4], o;
        o.x = a.x + b.x; o.y = a.y + b.y; o.z = a.z + b.z; o.w = a.w + b.w;
        reinterpret_cast<float4*>(g_bv2)[i] = o;
    }
}

// ---------------------------------------------------------------------------
// Tiled fp32 SGEMM: C[m,n] = alpha * sum_k A(k,m)*B(k,n) + bias[m]
//   A_MK: A stored [M,K] row-major (element (k,m) = A[m*K+k]) else [K,M]
//   B_NK: B stored [N,K] row-major (element (k,n) = B[n*K+k]) else [K,N]
// All of M,N,K are multiples of 128/16 here -> no bounds checks.
// 128x128 block tile, K-tile 16, 256 threads, 8x8 per-thread microtile,
// double-buffered shared memory.
// ---------------------------------------------------------------------------
template<bool A_MK, bool B_NK>
__global__ void __launch_bounds__(256)
sgemm_kernel(const float* __restrict__ Ag, const float* __restrict__ Bg,
             float* __restrict__ Cg, const float* __restrict__ bias,
             float alpha, int M, int N, int K,
             size_t sA, size_t sB, size_t sC)
{
    __shared__ float As[2][16][132];
    __shared__ float Bs[2][16][132];

    const int tid = threadIdx.x;
    const int m0 = blockIdx.y * 128;
    const int n0 = blockIdx.x * 128;
    const float* A = Ag + sA * blockIdx.z;
    const float* B = Bg + sB * blockIdx.z;
    float* Cb = Cg + sC * blockIdx.z;

    float acc[8][8];
#pragma unroll
    for (int i = 0; i < 8; ++i)
#pragma unroll
        for (int j = 0; j < 8; ++j) acc[i][j] = 0.f;

    float4 ra[2], rb[2];

    auto fetchA = [&](int kt) {
#pragma unroll
        for (int it = 0; it < 2; ++it) {
            if (A_MK) {
                int m = (tid >> 2) + 64 * it;
                int k = (tid & 3) * 4;
                ra[it] = *reinterpret_cast<const float4*>(
                    &A[(size_t)(m0 + m) * K + kt * 16 + k]);
            } else {
                int k  = (tid >> 5) + 8 * it;
                int m4 = (tid & 31) * 4;
                ra[it] = *reinterpret_cast<const float4*>(
                    &A[(size_t)(kt * 16 + k) * M + m0 + m4]);
            }
        }
    };
    auto storeA = [&](int buf) {
#pragma unroll
        for (int it = 0; it < 2; ++it) {
            if (A_MK) {
                int m = (tid >> 2) + 64 * it;
                int k = (tid & 3) * 4;
                As[buf][k + 0][m] = ra[it].x;
                As[buf][k + 1][m] = ra[it].y;
                As[buf][k + 2][m] = ra[it].z;
                As[buf][k + 3][m] = ra[it].w;
            } else {
                int k  = (tid >> 5) + 8 * it;
                int m4 = (tid & 31) * 4;
                *reinterpret_cast<float4*>(&As[buf][k][m4]) = ra[it];
            }
        }
    };
    auto fetchB = [&](int kt) {
#pragma unroll
        for (int it = 0; it < 2; ++it) {
            if (B_NK) {
                int n = (tid >> 2) + 64 * it;
                int k = (tid & 3) * 4;
                rb[it] = *reinterpret_cast<const float4*>(
                    &B[(size_t)(n0 + n) * K + kt * 16 + k]);
            } else {
                int k  = (tid >> 5) + 8 * it;
                int n4 = (tid & 31) * 4;
                rb[it] = *reinterpret_cast<const float4*>(
                    &B[(size_t)(kt * 16 + k) * N + n0 + n4]);
            }
        }
    };
    auto storeB = [&](int buf) {
#pragma unroll
        for (int it = 0; it < 2; ++it) {
            if (B_NK) {
                int n = (tid >> 2) + 64 * it;
                int k = (tid & 3) * 4;
                Bs[buf][k + 0][n] = rb[it].x;
                Bs[buf][k + 1][n] = rb[it].y;
                Bs[buf][k + 2][n] = rb[it].z;
                Bs[buf][k + 3][n] = rb[it].w;
            } else {
                int k  = (tid >> 5) + 8 * it;
                int n4 = (tid & 31) * 4;
                *reinterpret_cast<float4*>(&Bs[buf][k][n4]) = rb[it];
            }
        }
    };

    const int tx = tid & 15, ty = tid >> 4;
    const int nkt = K / 16;

    fetchA(0); fetchB(0);
    storeA(0); storeB(0);
    __syncthreads();

    for (int kt = 0; kt < nkt; ++kt) {
        const int buf = kt & 1;
        if (kt + 1 < nkt) { fetchA(kt + 1); fetchB(kt + 1); }

#pragma unroll
        for (int kk = 0; kk < 16; ++kk) {
            float a[8], b[8];
            *reinterpret_cast<float4*>(&a[0]) =
                *reinterpret_cast<const float4*>(&As[buf][kk][ty * 8]);
            *reinterpret_cast<float4*>(&a[4]) =
                *reinterpret_cast<const float4*>(&As[buf][kk][ty * 8 + 4]);
            *reinterpret_cast<float4*>(&b[0]) =
                *reinterpret_cast<const float4*>(&Bs[buf][kk][tx * 8]);
            *reinterpret_cast<float4*>(&b[4]) =
                *reinterpret_cast<const float4*>(&Bs[buf][kk][tx * 8 + 4]);
#pragma unroll
            for (int i = 0; i < 8; ++i)
#pragma unroll
                for (int j = 0; j < 8; ++j)
                    acc[i][j] = fmaf(a[i], b[j], acc[i][j]);
        }

        if (kt + 1 < nkt) { storeA(buf ^ 1); storeB(buf ^ 1); }
        __syncthreads();
    }

#pragma unroll
    for (int i = 0; i < 8; ++i) {
        const int m = m0 + ty * 8 + i;
        const float bias_v = bias ? bias[m] : 0.f;
        float4 o0, o1;
        o0.x = acc[i][0] * alpha + bias_v;
        o0.y = acc[i][1] * alpha + bias_v;
        o0.z = acc[i][2] * alpha + bias_v;
        o0.w = acc[i][3] * alpha + bias_v;
        o1.x = acc[i][4] * alpha + bias_v;
        o1.y = acc[i][5] * alpha + bias_v;
        o1.z = acc[i][6] * alpha + bias_v;
        o1.w = acc[i][7] * alpha + bias_v;
        *reinterpret_cast<float4*>(&Cb[(size_t)m * N + n0 + tx * 8])     = o0;
        *reinterpret_cast<float4*>(&Cb[(size_t)m * N + n0 + tx * 8 + 4]) = o1;
    }
}

// ---------------------------------------------------------------------------
// Row softmax in place on attn [BATCH*NPIX rows][NPIX]
// ---------------------------------------------------------------------------
__global__ void softmax_kernel(float* __restrict__ attn)
{
    float* p = attn + (size_t)blockIdx.x * NPIX;
    const int t = threadIdx.x;
    float v[16];
    float mx = -1e30f;
#pragma unroll
    for (int j = 0; j < 16; ++j) {
        v[j] = p[t + 256 * j];
        mx = fmaxf(mx, v[j]);
    }
    __shared__ float sred[8];
#pragma unroll
    for (int o = 16; o; o >>= 1)
        mx = fmaxf(mx, __shfl_xor_sync(0xffffffffu, mx, o));
    if ((t & 31) == 0) sred[t >> 5] = mx;
    __syncthreads();
    mx = sred[0];
#pragma unroll
    for (int k = 1; k < 8; ++k) mx = fmaxf(mx, sred[k]);

    float s = 0.f;
#pragma unroll
    for (int j = 0; j < 16; ++j) {
        v[j] = __expf(v[j] - mx);
        s += v[j];
    }
#pragma unroll
    for (int o = 16; o; o >>= 1)
        s += __shfl_xor_sync(0xffffffffu, s, o);
    __syncthreads();
    if ((t & 31) == 0) sred[t >> 5] = s;
    __syncthreads();
    s = 0.f;
#pragma unroll
    for (int k = 0; k < 8; ++k) s += sred[k];

    const float inv = 1.f / s;
#pragma unroll
    for (int j = 0; j < 16; ++j) p[t + 256 * j] = v[j] * inv;
}

// ---------------------------------------------------------------------------
// kernel_launch
// Inputs (metadata order): f_rgb, f_i, wq, bq, wk, bk, wv, bv
// Output layout: [f_final | f_rgb | f_i | attn] flattened fp32
// ---------------------------------------------------------------------------
extern "C" void kernel_launch(void* const* d_in, const int* in_sizes, int n_in,
                              void* d_out, int out_size)
{
    const float* f_rgb = (const float*)d_in[0];
    const float* f_i   = (const float*)d_in[1];
    const float* wq    = (const float*)d_in[2];
    const float* bq    = (const float*)d_in[3];
    const float* wk    = (const float*)d_in[4];
    const float* bk    = (const float*)d_in[5];
    const float* wv    = (const float*)d_in[6];
    const float* bv    = (const float*)d_in[7];
    float* out = (float*)d_out;

    float *X, *Q, *Kp, *V2, *wv2, *bv2;
    cudaGetSymbolAddress((void**)&X,   g_X);
    cudaGetSymbolAddress((void**)&Q,   g_Q);
    cudaGetSymbolAddress((void**)&Kp,  g_K);
    cudaGetSymbolAddress((void**)&V2,  g_V2);
    cudaGetSymbolAddress((void**)&wv2, g_wv2);
    cudaGetSymbolAddress((void**)&bv2, g_bv2);

    float* f_final = out;
    float* attn    = out + (size_t)3 * BATCH * C2 * NPIX;  // after f_final,f_rgb,f_i

    // 1) copies into output + pack concat X
    pack_copy_kernel<<<16384, 256>>>((const float4*)f_rgb, (const float4*)f_i,
                                     (float4*)out);
    // 2) fold V weights
    wsum_kernel<<<8192, 256>>>((const float4*)wv, (const float4*)bv);

    const size_t sX = (size_t)2 * C2 * NPIX;   // per-batch X stride
    const size_t sQ = (size_t)C2 * NPIX;       // per-batch Q/K/V2/f_final stride
    const size_t sS = (size_t)NPIX * NPIX;     // per-batch attn stride

    // 3) projections: Q = wq@X + bq, K = wk@X + bk, V2 = wv2@X + bv2
    dim3 gQKV(NPIX / 128, C2 / 128, BATCH);
    sgemm_kernel<true, false><<<gQKV, 256>>>(wq,  X, Q,  bq,  1.f, C2, NPIX, 2 * C2, 0, sX, sQ);
    sgemm_kernel<true, false><<<gQKV, 256>>>(wk,  X, Kp, bk,  1.f, C2, NPIX, 2 * C2, 0, sX, sQ);
    sgemm_kernel<true, false><<<gQKV, 256>>>(wv2, X, V2, bv2, 1.f, C2, NPIX, 2 * C2, 0, sX, sQ);

    // 4) S[n,m] = (1/64) * sum_c Q[c,n]K[c,m]  (written into attn region)
    dim3 gS(NPIX / 128, NPIX / 128, BATCH);
    sgemm_kernel<false, false><<<gS, 256>>>(Q, Kp, attn, nullptr, 1.f / 64.f,
                                            NPIX, NPIX, C2, sQ, sQ, sS);

    // 5) row softmax in place
    softmax_kernel<<<BATCH * NPIX, 256>>>(attn);

    // 6) f_final[c,n] = sum_m V2[c,m] * attn[n,m]
    sgemm_kernel<true, true><<<gQKV, 256>>>(V2, attn, f_final, nullptr, 1.f,
                                            C2, NPIX, 2 * C2, sQ, sS, sQ);
}

// round 3
// speedup vs baseline: 3.2289x; 3.2289x over previous
#include <cuda_runtime.h>
#include <cuda_fp16.h>
#include <cstdint>

#define C2    2048
#define NPIX  4096
#define BATCH 2

typedef __half fp16;

// ---------------------------------------------------------------------------
// Static device scratch (no allocations anywhere)
// ---------------------------------------------------------------------------
__device__ fp16 g_Xt_h[(size_t)BATCH * NPIX * 2 * C2];   // [b][pix][4096 ch]
__device__ fp16 g_Xt_l[(size_t)BATCH * NPIX * 2 * C2];
__device__ fp16 g_wq_h[(size_t)C2 * 2 * C2];
__device__ fp16 g_wq_l[(size_t)C2 * 2 * C2];
__device__ fp16 g_wk_h[(size_t)C2 * 2 * C2];
__device__ fp16 g_wk_l[(size_t)C2 * 2 * C2];
__device__ fp16 g_wv2_h[(size_t)C2 * 2 * C2];            // folded V weights
__device__ fp16 g_wv2_l[(size_t)C2 * 2 * C2];
__device__ float g_bv2[C2];
__device__ fp16 g_Qt_h[(size_t)BATCH * NPIX * C2];       // [b][pix][ch]
__device__ fp16 g_Qt_l[(size_t)BATCH * NPIX * C2];
__device__ fp16 g_Kt_h[(size_t)BATCH * NPIX * C2];
__device__ fp16 g_Kt_l[(size_t)BATCH * NPIX * C2];
__device__ fp16 g_V2_h[(size_t)BATCH * C2 * NPIX];       // [b][ch][pix]
__device__ fp16 g_V2_l[(size_t)BATCH * C2 * NPIX];
__device__ fp16 g_At_h[(size_t)BATCH * NPIX * NPIX];     // attn fp16 pair
__device__ fp16 g_At_l[(size_t)BATCH * NPIX * NPIX];

// ---------------------------------------------------------------------------
// helpers
// ---------------------------------------------------------------------------
__device__ __forceinline__ uint32_t smem_u32(const void* p) {
    uint32_t a;
    asm("{ .reg .u64 t; cvta.to.shared.u64 t, %1; cvt.u32.u64 %0, t; }"
        : "=r"(a) : "l"(p));
    return a;
}
__device__ __forceinline__ uint32_t swz(uint32_t b) {       // 128B-row swizzle
    return b ^ ((b >> 3) & 0x70);
}
__device__ __forceinline__ void cp_async16(uint32_t dst, const void* src) {
    asm volatile("cp.async.cg.shared.global [%0], [%1], 16;\n"
                 :: "r"(dst), "l"(src) : "memory");
}
__device__ __forceinline__ void ldsm_x4(uint32_t* r, uint32_t addr) {
    asm volatile("ldmatrix.sync.aligned.m8n8.x4.shared.b16 {%0,%1,%2,%3}, [%4];"
                 : "=r"(r[0]), "=r"(r[1]), "=r"(r[2]), "=r"(r[3]) : "r"(addr));
}
__device__ __forceinline__ void mma16816(float* d, const uint32_t* a,
                                         const uint32_t* b) {
    asm volatile(
        "mma.sync.aligned.m16n8k16.row.col.f32.f16.f16.f32 "
        "{%0,%1,%2,%3}, {%4,%5,%6,%7}, {%8,%9}, {%0,%1,%2,%3};"
        : "+f"(d[0]), "+f"(d[1]), "+f"(d[2]), "+f"(d[3])
        : "r"(a[0]), "r"(a[1]), "r"(a[2]), "r"(a[3]), "r"(b[0]), "r"(b[1]));
}
__device__ __forceinline__ void split_h(float v, fp16& h, fp16& l) {
    h = __float2half_rn(v);
    l = __float2half_rn(v - __half2float(h));
}

// ---------------------------------------------------------------------------
// Pack + transpose: f_rgb/f_i -> fp32 output copies and Xt hi/lo (fp16)
// grid (NPIX/32, C2/32, BATCH*2), block (32,8)
// ---------------------------------------------------------------------------
__global__ void pack_transpose_kernel(const float* __restrict__ frgb,
                                      const float* __restrict__ fi,
                                      float* __restrict__ out)
{
    __shared__ float tile[32][33];
    const int s = blockIdx.z & 1, b = blockIdx.z >> 1;
    const float* src = s ? fi : frgb;
    const int pix0 = blockIdx.x * 32, ch0 = blockIdx.y * 32;
    const size_t base = (size_t)b * C2 * NPIX;
    const size_t PER  = (size_t)BATCH * C2 * NPIX;
    const int tx = threadIdx.x, ty = threadIdx.y;
#pragma unroll
    for (int i = 0; i < 4; ++i) {
        const int ch = ch0 + ty + i * 8;
        const size_t idx = base + (size_t)ch * NPIX + pix0 + tx;
        float v = src[idx];
        out[PER * (1 + s) + idx] = v;          // f_rgb / f_i copy
        tile[ty + i * 8][tx] = v;
    }
    __syncthreads();
    const size_t xbase = (size_t)b * NPIX * (2 * C2) + (size_t)s * C2;
#pragma unroll
    for (int i = 0; i < 4; ++i) {
        const int pix = pix0 + ty + i * 8;
        float v = tile[tx][ty + i * 8];
        fp16 h, l; split_h(v, h, l);
        const size_t idx = xbase + (size_t)pix * (2 * C2) + ch0 + tx;
        g_Xt_h[idx] = h;
        g_Xt_l[idx] = l;
    }
}

// ---------------------------------------------------------------------------
// Weight prep: split wq/wk, fold+split wv, fold bv
// ---------------------------------------------------------------------------
__global__ void weights_prep_kernel(const float* __restrict__ wq,
                                    const float* __restrict__ wk,
                                    const float* __restrict__ wv,
                                    const float* __restrict__ bv)
{
    const size_t NW = (size_t)C2 * 2 * C2;
    size_t i = (size_t)blockIdx.x * blockDim.x + threadIdx.x;
    if (i < NW) {
        fp16 h, l;
        split_h(wq[i], h, l);              g_wq_h[i] = h;  g_wq_l[i] = l;
        split_h(wk[i], h, l);              g_wk_h[i] = h;  g_wk_l[i] = l;
        split_h(wv[i] + wv[i + NW], h, l); g_wv2_h[i] = h; g_wv2_l[i] = l;
    }
    if (i < C2) g_bv2[i] = bv[i] + bv[i + C2];
}

// ---------------------------------------------------------------------------
// HMMA GEMM:  D[M,N] = alpha * A[M,K] @ B[N,K]^T (+bias), fp16 hi/lo 3-product
// CTA tile 128x128, kTile 64, 8 warps (warp tile 64x32), 2-stage cp.async.
// MODE 0: out fp16 hi/lo pair, row-major; MODE 1: out f32 row-major * alpha.
// ---------------------------------------------------------------------------
static constexpr int TILE16K  = 16384;                // one 128x64 fp16 tile
static constexpr int STAGE_B  = 4 * TILE16K;          // Ah, Al, Bh, Bl
static constexpr int GEMM_SMEM = 2 * STAGE_B + 256;

template<int MODE>
__global__ void __launch_bounds__(256, 1)
hgemm(const fp16* __restrict__ Ah, const fp16* __restrict__ Al,
      const fp16* __restrict__ Bh, const fp16* __restrict__ Bl,
      size_t sAb, size_t sBb, int K,
      void* __restrict__ out0v, void* __restrict__ out1v,
      int ldo, size_t sOb, float alpha,
      const float* __restrict__ bias_m, const float* __restrict__ bias_n)
{
    extern __shared__ __align__(128) char dsm[];
    const uint32_t smbase = (smem_u32(dsm) + 127u) & ~127u;

    const int tid  = threadIdx.x;
    const int lane = tid & 31, warp = tid >> 5;
    const int m0 = blockIdx.y * 128;
    const int n0 = blockIdx.x * 128;
    const int b  = blockIdx.z;
    Ah += sAb * b;  Al += sAb * b;
    Bh += sBb * b;  Bl += sBb * b;

    const int wm = (warp >> 2) * 64;     // warp M offset in tile
    const int wn = (warp & 3) * 32;      // warp N offset in tile

    float acc[4][4][4];
#pragma unroll
    for (int i = 0; i < 4; ++i)
#pragma unroll
        for (int j = 0; j < 4; ++j)
#pragma unroll
            for (int q = 0; q < 4; ++q) acc[i][j][q] = 0.f;

    // ldmatrix per-lane addressing
    const int arow = wm + (lane & 15);        // row in 128-row A tile
    const int brow = wn + (lane & 15);        // row in B tile (n 0-15 of warp)
    const int hk   = lane >> 4;               // k half (16B unit)
    const int sxa  = arow & 7;
    const int sxb  = brow & 7;                // (brow+16)&7 == sxb

    auto load_stage = [&](int kt, int buf) {
        const uint32_t sb = smbase + buf * STAGE_B;
        const int k0 = kt * 64;
        const fp16* gp[4] = {Ah, Al, Bh, Bl};
        const int   r0[4] = {m0, m0, n0, n0};
#pragma unroll
        for (int t = 0; t < 4; ++t) {
            const uint32_t tb = sb + t * TILE16K;
            const fp16* g = gp[t];
            const int row0 = r0[t];
#pragma unroll
            for (int j = 0; j < 4; ++j) {
                int idx = tid + j * 256;
                int r = idx >> 3, c = idx & 7;
                cp_async16(tb + swz((uint32_t)(r * 128 + c * 16)),
                           g + (size_t)(row0 + r) * K + k0 + c * 8);
            }
        }
        asm volatile("cp.async.commit_group;" ::: "memory");
    };

    const int NK = K / 64;
    load_stage(0, 0);

    for (int kt = 0; kt < NK; ++kt) {
        const int buf = kt & 1;
        asm volatile("cp.async.wait_group 0;" ::: "memory");
        __syncthreads();
        if (kt + 1 < NK) load_stage(kt + 1, buf ^ 1);

        const uint32_t sb = smbase + buf * STAGE_B;
        const uint32_t aH = sb, aL = sb + TILE16K;
        const uint32_t bH = sb + 2 * TILE16K, bL = sb + 3 * TILE16K;

#pragma unroll
        for (int kc = 0; kc < 4; ++kc) {
            const uint32_t colA = (uint32_t)(((kc * 2 + hk) ^ sxa) << 4);
            const uint32_t colB = (uint32_t)(((kc * 2 + hk) ^ sxb) << 4);
            uint32_t a1[4][4], a2[4][4], b1[4][2], b2[4][2], t[4];

#pragma unroll
            for (int mi = 0; mi < 4; ++mi)
                ldsm_x4(a1[mi], aH + (uint32_t)((arow + mi * 16) * 128) + colA);
            ldsm_x4(t, bH + (uint32_t)(brow * 128) + colB);
            b1[0][0] = t[0]; b1[0][1] = t[2]; b1[1][0] = t[1]; b1[1][1] = t[3];
            ldsm_x4(t, bH + (uint32_t)((brow + 16) * 128) + colB);
            b1[2][0] = t[0]; b1[2][1] = t[2]; b1[3][0] = t[1]; b1[3][1] = t[3];
#pragma unroll
            for (int mi = 0; mi < 4; ++mi)
#pragma unroll
                for (int ni = 0; ni < 4; ++ni)
                    mma16816(acc[mi][ni], a1[mi], b1[ni]);      // hh

            ldsm_x4(t, bL + (uint32_t)(brow * 128) + colB);
            b2[0][0] = t[0]; b2[0][1] = t[2]; b2[1][0] = t[1]; b2[1][1] = t[3];
            ldsm_x4(t, bL + (uint32_t)((brow + 16) * 128) + colB);
            b2[2][0] = t[0]; b2[2][1] = t[2]; b2[3][0] = t[1]; b2[3][1] = t[3];
#pragma unroll
            for (int mi = 0; mi < 4; ++mi)
#pragma unroll
                for (int ni = 0; ni < 4; ++ni)
                    mma16816(acc[mi][ni], a1[mi], b2[ni]);      // hl

#pragma unroll
            for (int mi = 0; mi < 4; ++mi)
                ldsm_x4(a2[mi], aL + (uint32_t)((arow + mi * 16) * 128) + colA);
#pragma unroll
            for (int mi = 0; mi < 4; ++mi)
#pragma unroll
                for (int ni = 0; ni < 4; ++ni)
                    mma16816(acc[mi][ni], a2[mi], b1[ni]);      // lh
        }
        __syncthreads();
    }

    // ------------------------------- epilogue ------------------------------
    const int r0 = m0 + wm + (lane >> 2);
    const int c0 = n0 + wn + (lane & 3) * 2;
#pragma unroll
    for (int mi = 0; mi < 4; ++mi) {
        const int rA = r0 + mi * 16, rB = rA + 8;
        float bmA = 0.f, bmB = 0.f;
        if (MODE == 0 && bias_m) { bmA = bias_m[rA]; bmB = bias_m[rB]; }
#pragma unroll
        for (int ni = 0; ni < 4; ++ni) {
            const int col = c0 + ni * 8;
            if (MODE == 1) {
                float* o = (float*)out0v + sOb * b;
                float2 u;
                u.x = acc[mi][ni][0] * alpha; u.y = acc[mi][ni][1] * alpha;
                *(float2*)(o + (size_t)rA * ldo + col) = u;
                u.x = acc[mi][ni][2] * alpha; u.y = acc[mi][ni][3] * alpha;
                *(float2*)(o + (size_t)rB * ldo + col) = u;
            } else {
                fp16* oh = (fp16*)out0v + sOb * b;
                fp16* ol = (fp16*)out1v + sOb * b;
                float bn0 = 0.f, bn1 = 0.f;
                if (bias_n) { bn0 = bias_n[col]; bn1 = bias_n[col + 1]; }
                float v0 = acc[mi][ni][0] + bmA + bn0;
                float v1 = acc[mi][ni][1] + bmA + bn1;
                float v2 = acc[mi][ni][2] + bmB + bn0;
                float v3 = acc[mi][ni][3] + bmB + bn1;
                fp16 h0, l0, h1, l1, h2, l2, h3, l3;
                split_h(v0, h0, l0); split_h(v1, h1, l1);
                split_h(v2, h2, l2); split_h(v3, h3, l3);
                *(__half2*)(oh + (size_t)rA * ldo + col) = __halves2half2(h0, h1);
                *(__half2*)(ol + (size_t)rA * ldo + col) = __halves2half2(l0, l1);
                *(__half2*)(oh + (size_t)rB * ldo + col) = __halves2half2(h2, h3);
                *(__half2*)(ol + (size_t)rB * ldo + col) = __halves2half2(l2, l3);
            }
        }
    }
}

// ---------------------------------------------------------------------------
// Row softmax: f32 in/out on attn, plus fp16 hi/lo pair for the final GEMM
// ---------------------------------------------------------------------------
__global__ void softmax_kernel(float* __restrict__ attn,
                               fp16* __restrict__ ah, fp16* __restrict__ al)
{
    const size_t roff = (size_t)blockIdx.x * NPIX;
    float* p = attn + roff;
    const int t = threadIdx.x;
    float v[16];
    float mx = -1e30f;
#pragma unroll
    for (int j = 0; j < 16; ++j) {
        v[j] = p[t + 256 * j];
        mx = fmaxf(mx, v[j]);
    }
    __shared__ float sred[8];
#pragma unroll
    for (int o = 16; o; o >>= 1)
        mx = fmaxf(mx, __shfl_xor_sync(0xffffffffu, mx, o));
    if ((t & 31) == 0) sred[t >> 5] = mx;
    __syncthreads();
    mx = sred[0];
#pragma unroll
    for (int k = 1; k < 8; ++k) mx = fmaxf(mx, sred[k]);

    float s = 0.f;
#pragma unroll
    for (int j = 0; j < 16; ++j) {
        v[j] = __expf(v[j] - mx);
        s += v[j];
    }
#pragma unroll
    for (int o = 16; o; o >>= 1)
        s += __shfl_xor_sync(0xffffffffu, s, o);
    __syncthreads();
    if ((t & 31) == 0) sred[t >> 5] = s;
    __syncthreads();
    s = 0.f;
#pragma unroll
    for (int k = 0; k < 8; ++k) s += sred[k];

    const float inv = 1.f / s;
#pragma unroll
    for (int j = 0; j < 16; ++j) {
        const int idx = t + 256 * j;
        float o = v[j] * inv;
        p[idx] = o;
        fp16 h, l; split_h(o, h, l);
        ah[roff + idx] = h;
        al[roff + idx] = l;
    }
}

// ---------------------------------------------------------------------------
// kernel_launch
// Inputs: f_rgb, f_i, wq, bq, wk, bk, wv, bv
// Output: [f_final | f_rgb | f_i | attn] fp32
// ---------------------------------------------------------------------------
extern "C" void kernel_launch(void* const* d_in, const int* in_sizes, int n_in,
                              void* d_out, int out_size)
{
    const float* f_rgb = (const float*)d_in[0];
    const float* f_i   = (const float*)d_in[1];
    const float* wq    = (const float*)d_in[2];
    const float* bq    = (const float*)d_in[3];
    const float* wk    = (const float*)d_in[4];
    const float* bk    = (const float*)d_in[5];
    const float* wv    = (const float*)d_in[6];
    const float* bv    = (const float*)d_in[7];
    float* out = (float*)d_out;

    cudaFuncSetAttribute(hgemm<0>, cudaFuncAttributeMaxDynamicSharedMemorySize, GEMM_SMEM);
    cudaFuncSetAttribute(hgemm<1>, cudaFuncAttributeMaxDynamicSharedMemorySize, GEMM_SMEM);

    fp16 *Xh, *Xl, *qh, *ql, *kh, *kl, *vh, *vl;
    fp16 *Qh, *Ql, *Kh, *Kl, *Vh, *Vl, *Ath, *Atl;
    float* bv2;
    cudaGetSymbolAddress((void**)&Xh,  g_Xt_h);
    cudaGetSymbolAddress((void**)&Xl,  g_Xt_l);
    cudaGetSymbolAddress((void**)&qh,  g_wq_h);
    cudaGetSymbolAddress((void**)&ql,  g_wq_l);
    cudaGetSymbolAddress((void**)&kh,  g_wk_h);
    cudaGetSymbolAddress((void**)&kl,  g_wk_l);
    cudaGetSymbolAddress((void**)&vh,  g_wv2_h);
    cudaGetSymbolAddress((void**)&vl,  g_wv2_l);
    cudaGetSymbolAddress((void**)&Qh,  g_Qt_h);
    cudaGetSymbolAddress((void**)&Ql,  g_Qt_l);
    cudaGetSymbolAddress((void**)&Kh,  g_Kt_h);
    cudaGetSymbolAddress((void**)&Kl,  g_Kt_l);
    cudaGetSymbolAddress((void**)&Vh,  g_V2_h);
    cudaGetSymbolAddress((void**)&Vl,  g_V2_l);
    cudaGetSymbolAddress((void**)&Ath, g_At_h);
    cudaGetSymbolAddress((void**)&Atl, g_At_l);
    cudaGetSymbolAddress((void**)&bv2, g_bv2);

    float* f_final = out;
    float* attn    = out + (size_t)3 * BATCH * C2 * NPIX;

    const size_t sX = (size_t)NPIX * 2 * C2;
    const size_t sQ = (size_t)NPIX * C2;
    const size_t sS = (size_t)NPIX * NPIX;

    // 1) copies + transpose/split X
    pack_transpose_kernel<<<dim3(NPIX / 32, C2 / 32, BATCH * 2), dim3(32, 8)>>>(
        f_rgb, f_i, out);
    // 2) weight split / fold
    weights_prep_kernel<<<(unsigned)((size_t)C2 * 2 * C2 / 256), 256>>>(wq, wk, wv, bv);

    // 3) projections: Qt[pix][ch], Kt[pix][ch], V2[ch][pix]
    hgemm<0><<<dim3(C2 / 128, NPIX / 128, BATCH), 256, GEMM_SMEM>>>(
        Xh, Xl, qh, ql, sX, 0, 2 * C2, Qh, Ql, C2, sQ, 1.f, nullptr, bq);
    hgemm<0><<<dim3(C2 / 128, NPIX / 128, BATCH), 256, GEMM_SMEM>>>(
        Xh, Xl, kh, kl, sX, 0, 2 * C2, Kh, Kl, C2, sQ, 1.f, nullptr, bk);
    hgemm<0><<<dim3(NPIX / 128, C2 / 128, BATCH), 256, GEMM_SMEM>>>(
        vh, vl, Xh, Xl, 0, sX, 2 * C2, Vh, Vl, NPIX, sQ, 1.f, bv2, nullptr);

    // 4) scores S[n][m] = QK/64 (f32 into attn region)
    hgemm<1><<<dim3(NPIX / 128, NPIX / 128, BATCH), 256, GEMM_SMEM>>>(
        Qh, Ql, Kh, Kl, sQ, sQ, C2, attn, nullptr, NPIX, sS, 1.f / 64.f,
        nullptr, nullptr);

    // 5) softmax (f32 out + fp16 pair)
    softmax_kernel<<<BATCH * NPIX, 256>>>(attn, Ath, Atl);

    // 6) f_final[c][n] = sum_m V2[c,m] attn[n,m]  (row-major f32 out)
    hgemm<1><<<dim3(NPIX / 128, C2 / 128, BATCH), 256, GEMM_SMEM>>>(
        Vh, Vl, Ath, Atl, sQ, sS, NPIX, f_final, nullptr, NPIX, sQ, 1.f,
        nullptr, nullptr);
}